// round 1
// baseline (speedup 1.0000x reference)
#include <cuda_runtime.h>
#include <math.h>
#include <stdint.h>

// Instant-NGP multires hash grid lookup.
// Inputs (metadata order): d_in[0] = x (N,3) f32, d_in[1] = tables (16, 2^19, 2) f32
// Output: (N, 32) f32 — 16 levels x 2 features, level-major within a point.

#define N_LVL 16
#define HASH_MASK 0x7FFFFu
#define TABLE_ROWS 524288  // 2^19

struct LevelParams {
    float    rm1[N_LVL];    // (float)(res - 1.0)
    float    upper[N_LVL];  // (float)(res - 1.0001)
    unsigned xmul[N_LVL];   // dense: 1        hash: prime0
    unsigned ymul[N_LVL];   // dense: res      hash: prime1
    unsigned zmul[N_LVL];   // dense: res^2    hash: prime2
    unsigned dense[N_LVL];  // 1 if dense linear index, 0 if xor-prime hash
};

__global__ void __launch_bounds__(256)
grid_encode_kernel(const float* __restrict__ x,
                   const float2* __restrict__ tables,
                   float2* __restrict__ out,
                   int npts, LevelParams P)
{
    long long tid = (long long)blockIdx.x * blockDim.x + threadIdx.x;
    int p   = (int)(tid >> 4);
    if (p >= npts) return;
    int lvl = (int)(tid & 15);

    // 16 consecutive threads share one point -> same-address L1 broadcasts
    float px = __ldg(x + 3 * p + 0);
    float py = __ldg(x + 3 * p + 1);
    float pz = __ldg(x + 3 * p + 2);

    float rm1 = P.rm1[lvl];
    float up  = P.upper[lvl];

    // coord = clip(x*(res-1), 0, res-1.0001)  (all f32, matching reference)
    float cx = fminf(fmaxf(px * rm1, 0.0f), up);
    float cy = fminf(fmaxf(py * rm1, 0.0f), up);
    float cz = fminf(fmaxf(pz * rm1, 0.0f), up);

    float fx = floorf(cx), fy = floorf(cy), fz = floorf(cz);
    float dx = cx - fx,    dy = cy - fy,    dz = cz - fz;
    float mx = 1.0f - dx,  my = 1.0f - dy,  mz = 1.0f - dz;

    unsigned ix = (unsigned)(int)fx;
    unsigned iy = (unsigned)(int)fy;
    unsigned iz = (unsigned)(int)fz;

    unsigned xm = P.xmul[lvl], ym = P.ymul[lvl], zm = P.zmul[lvl];
    bool isDense = (P.dense[lvl] != 0);

    // Per-axis key contributions for both corner positions on that axis.
    unsigned ax0 = ix * xm, ax1 = ax0 + xm;
    unsigned ay0 = iy * ym, ay1 = ay0 + ym;
    unsigned az0 = iz * zm, az1 = az0 + zm;

    // combine: dense -> a+b+c (always < 2^19, so mask is a no-op); hash -> (a^b^c)&mask
    #define CIDX(a,b,c) ((isDense ? ((a)+(b)+(c)) : ((a)^(b)^(c))) & HASH_MASK)
    unsigned i000 = CIDX(ax0, ay0, az0);
    unsigned i001 = CIDX(ax0, ay0, az1);
    unsigned i010 = CIDX(ax0, ay1, az0);
    unsigned i011 = CIDX(ax0, ay1, az1);
    unsigned i100 = CIDX(ax1, ay0, az0);
    unsigned i101 = CIDX(ax1, ay0, az1);
    unsigned i110 = CIDX(ax1, ay1, az0);
    unsigned i111 = CIDX(ax1, ay1, az1);
    #undef CIDX

    const float2* tab = tables + (size_t)lvl * TABLE_ROWS;

    // Issue all 8 gathers back-to-back (MLP=8) before consuming.
    float2 f000 = __ldg(tab + i000);
    float2 f001 = __ldg(tab + i001);
    float2 f010 = __ldg(tab + i010);
    float2 f011 = __ldg(tab + i011);
    float2 f100 = __ldg(tab + i100);
    float2 f101 = __ldg(tab + i101);
    float2 f110 = __ldg(tab + i110);
    float2 f111 = __ldg(tab + i111);

    // trilinear weights, corner order matches OFFSETS (bit2=x, bit1=y, bit0=z)
    float wmm = mx * my, wmy_ = mx * dy, wxm = dx * my, wxy = dx * dy;
    float w000 = wmm  * mz, w001 = wmm  * dz;
    float w010 = wmy_ * mz, w011 = wmy_ * dz;
    float w100 = wxm  * mz, w101 = wxm  * dz;
    float w110 = wxy  * mz, w111 = wxy  * dz;

    float ox = w000 * f000.x;
    float oy = w000 * f000.y;
    ox = fmaf(w001, f001.x, ox);  oy = fmaf(w001, f001.y, oy);
    ox = fmaf(w010, f010.x, ox);  oy = fmaf(w010, f010.y, oy);
    ox = fmaf(w011, f011.x, ox);  oy = fmaf(w011, f011.y, oy);
    ox = fmaf(w100, f100.x, ox);  oy = fmaf(w100, f100.y, oy);
    ox = fmaf(w101, f101.x, ox);  oy = fmaf(w101, f101.y, oy);
    ox = fmaf(w110, f110.x, ox);  oy = fmaf(w110, f110.y, oy);
    ox = fmaf(w111, f111.x, ox);  oy = fmaf(w111, f111.y, oy);

    // out[p, lvl] as float2 -> 16 consecutive threads cover one point's 128B row
    out[(size_t)p * N_LVL + lvl] = make_float2(ox, oy);
}

extern "C" void kernel_launch(void* const* d_in, const int* in_sizes, int n_in,
                              void* d_out, int out_size)
{
    const float*  x      = (const float*)d_in[0];
    const float2* tables = (const float2*)d_in[1];
    float2*       out    = (float2*)d_out;
    int npts = in_sizes[0] / 3;

    // Replicate reference level config exactly (same libm double chain as numpy).
    LevelParams P;
    const double b = exp((log(2048.0) - log(16.0)) / 15.0);
    const unsigned primes[3] = {3367900313u, 2654435761u, 805459861u};
    for (int i = 0; i < N_LVL; i++) {
        double r = floor(16.0 * pow(b, (double)i));
        bool dense = (r * r * r < 524288.0);   // table_size != MAX_ENTRY
        P.rm1[i]   = (float)(r - 1.0);
        P.upper[i] = (float)(r - 1.0001);
        if (dense) {
            unsigned R = (unsigned)r;
            P.xmul[i] = 1u;
            P.ymul[i] = R;
            P.zmul[i] = R * R;   // exact (res<=80, res^2<=6400, exact in f32 too)
            P.dense[i] = 1u;
        } else {
            P.xmul[i] = primes[0];
            P.ymul[i] = primes[1];
            P.zmul[i] = primes[2];
            P.dense[i] = 0u;
        }
    }

    long long total = (long long)npts * N_LVL;
    int threads = 256;
    long long blocks = (total + threads - 1) / threads;
    grid_encode_kernel<<<(unsigned)blocks, threads>>>(x, tables, out, npts, P);
}

// round 2
// speedup vs baseline: 1.3355x; 1.3355x over previous
#include <cuda_runtime.h>
#include <math.h>
#include <stdint.h>

// Instant-NGP multires hash grid lookup, spatially-sorted variant.
// d_in[0] = x (N,3) f32, d_in[1] = tables (16, 2^19, 2) f32
// out: (N, 32) f32.
//
// Pipeline (all graph-capturable, no allocations):
//  1) zero histogram
//  2) per-point 64^3 cell key + histogram (RED)
//  3) 3-kernel exclusive scan over 262144 bins
//  4) scatter points (coords + orig index as float4) into sorted order
//  5) main kernel: warp = (32 sorted points, one level) -> coalesced gathers;
//     SMEM-staged output so each point's 128B row is written coalesced.

#define N_LVL 16
#define HASH_MASK 0x7FFFFu
#define TABLE_ROWS 524288
#define MAXPTS 2000000
#define SORT_RES 64
#define NBINS (SORT_RES * SORT_RES * SORT_RES)  // 262144
#define SCAN_BLK 1024
#define NSCAN_BLKS (NBINS / SCAN_BLK)           // 256

struct LevelParams {
    float    rm1[N_LVL];
    float    upper[N_LVL];
    unsigned xmul[N_LVL];
    unsigned ymul[N_LVL];
    unsigned zmul[N_LVL];
    unsigned dense[N_LVL];
};

// Scratch (static device globals; allowed, ~41 MB total)
__device__ unsigned g_hist[NBINS];
__device__ unsigned g_ofs[NBINS];
__device__ unsigned g_sums[NSCAN_BLKS];
__device__ unsigned g_key[MAXPTS];
__device__ float4   g_pts[MAXPTS];   // sorted {x,y,z, bitcast(orig_idx)}

// ---------------- sort kernels ----------------

__global__ void k_zero_hist()
{
    int i = blockIdx.x * blockDim.x + threadIdx.x;
    if (i < NBINS) g_hist[i] = 0u;
}

__global__ void k_hist(const float* __restrict__ x, int n)
{
    int p = blockIdx.x * blockDim.x + threadIdx.x;
    if (p >= n) return;
    float px = x[3 * p + 0], py = x[3 * p + 1], pz = x[3 * p + 2];
    int ix = min(max((int)(px * SORT_RES), 0), SORT_RES - 1);
    int iy = min(max((int)(py * SORT_RES), 0), SORT_RES - 1);
    int iz = min(max((int)(pz * SORT_RES), 0), SORT_RES - 1);
    unsigned key = (unsigned)(ix + SORT_RES * (iy + SORT_RES * iz));  // x fastest
    g_key[p] = key;
    atomicAdd(&g_hist[key], 1u);
}

__global__ void __launch_bounds__(SCAN_BLK) k_scan1()
{
    __shared__ unsigned s[SCAN_BLK];
    int t = threadIdx.x;
    int i = blockIdx.x * SCAN_BLK + t;
    unsigned v = g_hist[i];
    s[t] = v;
    __syncthreads();
    for (int off = 1; off < SCAN_BLK; off <<= 1) {
        unsigned a = (t >= off) ? s[t - off] : 0u;
        __syncthreads();
        s[t] += a;
        __syncthreads();
    }
    g_ofs[i] = s[t] - v;  // exclusive within block
    if (t == SCAN_BLK - 1) g_sums[blockIdx.x] = s[t];
}

__global__ void __launch_bounds__(NSCAN_BLKS) k_scan2()
{
    __shared__ unsigned s[NSCAN_BLKS];
    int t = threadIdx.x;
    unsigned v = g_sums[t];
    s[t] = v;
    __syncthreads();
    for (int off = 1; off < NSCAN_BLKS; off <<= 1) {
        unsigned a = (t >= off) ? s[t - off] : 0u;
        __syncthreads();
        s[t] += a;
        __syncthreads();
    }
    g_sums[t] = s[t] - v;  // exclusive
}

__global__ void k_scan3()
{
    int i = blockIdx.x * blockDim.x + threadIdx.x;
    if (i < NBINS) g_ofs[i] += g_sums[i / SCAN_BLK];
}

__global__ void k_scatter(const float* __restrict__ x, int n)
{
    int p = blockIdx.x * blockDim.x + threadIdx.x;
    if (p >= n) return;
    unsigned key = g_key[p];
    unsigned dst = atomicAdd(&g_ofs[key], 1u);
    g_pts[dst] = make_float4(x[3 * p + 0], x[3 * p + 1], x[3 * p + 2],
                             __uint_as_float((unsigned)p));
}

// ---------------- main encode ----------------

// block = 512 threads = 16 warps; warp w handles level w for 32 sorted points.
__global__ void __launch_bounds__(512)
k_encode_sorted(const float2* __restrict__ tables,
                float2* __restrict__ out, int n, LevelParams P)
{
    __shared__ float4 spts[32];
    __shared__ float2 stage[N_LVL][33];  // padded to dodge bank conflicts

    int t = threadIdx.x;
    int pbase = blockIdx.x * 32;

    if (t < 32) {
        int p = pbase + t;
        spts[t] = (p < n) ? g_pts[p] : make_float4(0.f, 0.f, 0.f, 0.f);
    }
    __syncthreads();

    int lane = t & 31;
    int lvl  = t >> 5;

    float4 pt = spts[lane];
    float px = pt.x, py = pt.y, pz = pt.z;

    float rm1 = P.rm1[lvl];
    float up  = P.upper[lvl];

    float cx = fminf(fmaxf(px * rm1, 0.0f), up);
    float cy = fminf(fmaxf(py * rm1, 0.0f), up);
    float cz = fminf(fmaxf(pz * rm1, 0.0f), up);

    float fx = floorf(cx), fy = floorf(cy), fz = floorf(cz);
    float dx = cx - fx,    dy = cy - fy,    dz = cz - fz;
    float mx = 1.0f - dx,  my = 1.0f - dy,  mz = 1.0f - dz;

    unsigned ix = (unsigned)(int)fx;
    unsigned iy = (unsigned)(int)fy;
    unsigned iz = (unsigned)(int)fz;

    unsigned xm = P.xmul[lvl], ym = P.ymul[lvl], zm = P.zmul[lvl];
    bool isDense = (P.dense[lvl] != 0);

    unsigned ax0 = ix * xm, ax1 = ax0 + xm;
    unsigned ay0 = iy * ym, ay1 = ay0 + ym;
    unsigned az0 = iz * zm, az1 = az0 + zm;

    #define CIDX(a,b,c) ((isDense ? ((a)+(b)+(c)) : ((a)^(b)^(c))) & HASH_MASK)
    unsigned i000 = CIDX(ax0, ay0, az0);
    unsigned i001 = CIDX(ax0, ay0, az1);
    unsigned i010 = CIDX(ax0, ay1, az0);
    unsigned i011 = CIDX(ax0, ay1, az1);
    unsigned i100 = CIDX(ax1, ay0, az0);
    unsigned i101 = CIDX(ax1, ay0, az1);
    unsigned i110 = CIDX(ax1, ay1, az0);
    unsigned i111 = CIDX(ax1, ay1, az1);
    #undef CIDX

    const float2* tab = tables + (size_t)lvl * TABLE_ROWS;

    float2 f000 = __ldg(tab + i000);
    float2 f001 = __ldg(tab + i001);
    float2 f010 = __ldg(tab + i010);
    float2 f011 = __ldg(tab + i011);
    float2 f100 = __ldg(tab + i100);
    float2 f101 = __ldg(tab + i101);
    float2 f110 = __ldg(tab + i110);
    float2 f111 = __ldg(tab + i111);

    float wmm = mx * my, wmy_ = mx * dy, wxm = dx * my, wxy = dx * dy;
    float w000 = wmm  * mz, w001 = wmm  * dz;
    float w010 = wmy_ * mz, w011 = wmy_ * dz;
    float w100 = wxm  * mz, w101 = wxm  * dz;
    float w110 = wxy  * mz, w111 = wxy  * dz;

    float ox = w000 * f000.x;
    float oy = w000 * f000.y;
    ox = fmaf(w001, f001.x, ox);  oy = fmaf(w001, f001.y, oy);
    ox = fmaf(w010, f010.x, ox);  oy = fmaf(w010, f010.y, oy);
    ox = fmaf(w011, f011.x, ox);  oy = fmaf(w011, f011.y, oy);
    ox = fmaf(w100, f100.x, ox);  oy = fmaf(w100, f100.y, oy);
    ox = fmaf(w101, f101.x, ox);  oy = fmaf(w101, f101.y, oy);
    ox = fmaf(w110, f110.x, ox);  oy = fmaf(w110, f110.y, oy);
    ox = fmaf(w111, f111.x, ox);  oy = fmaf(w111, f111.y, oy);

    stage[lvl][lane] = make_float2(ox, oy);
    __syncthreads();

    // Write-out: lanes 0..15 of each half-warp cover one point's full 128B row.
    int l  = t & 15;
    int pi = t >> 4;
    int p  = pbase + pi;
    if (p < n) {
        unsigned orig = __float_as_uint(spts[pi].w);
        out[(size_t)orig * N_LVL + l] = stage[l][pi];
    }
}

// ---------------- fallback direct kernel (npts > MAXPTS safety) ----------------

__global__ void __launch_bounds__(256)
k_encode_direct(const float* __restrict__ x, const float2* __restrict__ tables,
                float2* __restrict__ out, int npts, LevelParams P)
{
    long long tid = (long long)blockIdx.x * blockDim.x + threadIdx.x;
    int p = (int)(tid >> 4);
    if (p >= npts) return;
    int lvl = (int)(tid & 15);

    float px = __ldg(x + 3 * p + 0);
    float py = __ldg(x + 3 * p + 1);
    float pz = __ldg(x + 3 * p + 2);

    float rm1 = P.rm1[lvl], up = P.upper[lvl];
    float cx = fminf(fmaxf(px * rm1, 0.0f), up);
    float cy = fminf(fmaxf(py * rm1, 0.0f), up);
    float cz = fminf(fmaxf(pz * rm1, 0.0f), up);
    float fx = floorf(cx), fy = floorf(cy), fz = floorf(cz);
    float dx = cx - fx, dy = cy - fy, dz = cz - fz;
    float mx = 1.0f - dx, my = 1.0f - dy, mz = 1.0f - dz;
    unsigned ix = (unsigned)(int)fx, iy = (unsigned)(int)fy, iz = (unsigned)(int)fz;
    unsigned xm = P.xmul[lvl], ym = P.ymul[lvl], zm = P.zmul[lvl];
    bool isDense = (P.dense[lvl] != 0);
    unsigned ax0 = ix * xm, ax1 = ax0 + xm;
    unsigned ay0 = iy * ym, ay1 = ay0 + ym;
    unsigned az0 = iz * zm, az1 = az0 + zm;
    #define CIDX(a,b,c) ((isDense ? ((a)+(b)+(c)) : ((a)^(b)^(c))) & HASH_MASK)
    unsigned i000 = CIDX(ax0, ay0, az0), i001 = CIDX(ax0, ay0, az1);
    unsigned i010 = CIDX(ax0, ay1, az0), i011 = CIDX(ax0, ay1, az1);
    unsigned i100 = CIDX(ax1, ay0, az0), i101 = CIDX(ax1, ay0, az1);
    unsigned i110 = CIDX(ax1, ay1, az0), i111 = CIDX(ax1, ay1, az1);
    #undef CIDX
    const float2* tab = tables + (size_t)lvl * TABLE_ROWS;
    float2 f000 = __ldg(tab + i000), f001 = __ldg(tab + i001);
    float2 f010 = __ldg(tab + i010), f011 = __ldg(tab + i011);
    float2 f100 = __ldg(tab + i100), f101 = __ldg(tab + i101);
    float2 f110 = __ldg(tab + i110), f111 = __ldg(tab + i111);
    float wmm = mx * my, wmy_ = mx * dy, wxm = dx * my, wxy = dx * dy;
    float w000 = wmm * mz, w001 = wmm * dz, w010 = wmy_ * mz, w011 = wmy_ * dz;
    float w100 = wxm * mz, w101 = wxm * dz, w110 = wxy * mz, w111 = wxy * dz;
    float ox = w000 * f000.x, oy = w000 * f000.y;
    ox = fmaf(w001, f001.x, ox); oy = fmaf(w001, f001.y, oy);
    ox = fmaf(w010, f010.x, ox); oy = fmaf(w010, f010.y, oy);
    ox = fmaf(w011, f011.x, ox); oy = fmaf(w011, f011.y, oy);
    ox = fmaf(w100, f100.x, ox); oy = fmaf(w100, f100.y, oy);
    ox = fmaf(w101, f101.x, ox); oy = fmaf(w101, f101.y, oy);
    ox = fmaf(w110, f110.x, ox); oy = fmaf(w110, f110.y, oy);
    ox = fmaf(w111, f111.x, ox); oy = fmaf(w111, f111.y, oy);
    out[(size_t)p * N_LVL + lvl] = make_float2(ox, oy);
}

// ---------------- host ----------------

extern "C" void kernel_launch(void* const* d_in, const int* in_sizes, int n_in,
                              void* d_out, int out_size)
{
    const float*  x      = (const float*)d_in[0];
    const float2* tables = (const float2*)d_in[1];
    float2*       out    = (float2*)d_out;
    int npts = in_sizes[0] / 3;

    LevelParams P;
    const double b = exp((log(2048.0) - log(16.0)) / 15.0);
    const unsigned primes[3] = {3367900313u, 2654435761u, 805459861u};
    for (int i = 0; i < N_LVL; i++) {
        double r = floor(16.0 * pow(b, (double)i));
        bool dense = (r * r * r < 524288.0);
        P.rm1[i]   = (float)(r - 1.0);
        P.upper[i] = (float)(r - 1.0001);
        if (dense) {
            unsigned R = (unsigned)r;
            P.xmul[i] = 1u; P.ymul[i] = R; P.zmul[i] = R * R; P.dense[i] = 1u;
        } else {
            P.xmul[i] = primes[0]; P.ymul[i] = primes[1]; P.zmul[i] = primes[2];
            P.dense[i] = 0u;
        }
    }

    if (npts > MAXPTS) {
        long long total = (long long)npts * N_LVL;
        long long blocks = (total + 255) / 256;
        k_encode_direct<<<(unsigned)blocks, 256>>>(x, tables, out, npts, P);
        return;
    }

    int pblocks = (npts + 255) / 256;

    k_zero_hist<<<NBINS / 1024, 1024>>>();
    k_hist<<<pblocks, 256>>>(x, npts);
    k_scan1<<<NSCAN_BLKS, SCAN_BLK>>>();
    k_scan2<<<1, NSCAN_BLKS>>>();
    k_scan3<<<NBINS / 1024, 1024>>>();
    k_scatter<<<pblocks, 256>>>(x, npts);

    int mblocks = (npts + 31) / 32;
    k_encode_sorted<<<mblocks, 512>>>(tables, out, npts, P);
}